// round 11
// baseline (speedup 1.0000x reference)
#include <cuda_runtime.h>
#include <math.h>

// ---------------------------------------------------------------------------
// GaussCrossEntropyLoss — two-pass, occupancy-optimized (6 blocks/SM pass 2).
// Pass 1 (k_stats): coord+segment -> per-cloud z stats.
// Pass 2 (k_loss):  pred(+ldcs)+coord+segment -> sum CE*focal*gauss;
//                   last block writes the mean and resets state (no init).
// ---------------------------------------------------------------------------

#define FULLMASK 0xFFFFFFFFu
#define MAXB 8
#define BIGF 3.402823466e+38f

// Static initializers == clean state; the last k_loss block restores them.
__device__ float g_gmax[MAXB] = {-BIGF,-BIGF,-BIGF,-BIGF,-BIGF,-BIGF,-BIGF,-BIGF};
__device__ float g_pmin[MAXB] = { BIGF, BIGF, BIGF, BIGF, BIGF, BIGF, BIGF, BIGF};
__device__ float g_zmin[MAXB] = { BIGF, BIGF, BIGF, BIGF, BIGF, BIGF, BIGF, BIGF};
__device__ float g_zmax[MAXB] = {-BIGF,-BIGF,-BIGF,-BIGF,-BIGF,-BIGF,-BIGF,-BIGF};
__device__ float g_acc[32];
__device__ int   g_done;

__device__ __forceinline__ void atomicMaxF(float* a, float v) {
    if (v >= 0.0f) atomicMax((int*)a, __float_as_int(v));
    else           atomicMin((unsigned int*)a, __float_as_uint(v));
}
__device__ __forceinline__ void atomicMinF(float* a, float v) {
    if (v >= 0.0f) atomicMin((int*)a, __float_as_int(v));
    else           atomicMax((unsigned int*)a, __float_as_uint(v));
}

__device__ __forceinline__ int batch_of(int i, const int* s_off) {
    int b = 0;
#pragma unroll
    for (int k = 0; k < MAXB; k++) b += (i >= s_off[k]);
    return b;
}

// ---------------------------------------------------------------------------
// Pass 1: per-cloud z statistics, 4 points per thread, <=32 regs
// ---------------------------------------------------------------------------
__global__ void __launch_bounds__(256, 8)
k_stats(const float* __restrict__ coord, const int* __restrict__ segment,
        const int* __restrict__ offset, int n, int nb)
{
    __shared__ int   s_off[MAXB];
    __shared__ float s_gmax[MAXB], s_pmin[MAXB], s_zmin[MAXB], s_zmax[MAXB];
    const int tid = threadIdx.x;
    if (tid < MAXB) {
        s_off[tid]  = (tid < nb) ? offset[tid] : 0x7FFFFFFF;
        s_gmax[tid] = -BIGF;  s_pmin[tid] = BIGF;
        s_zmin[tid] =  BIGF;  s_zmax[tid] = -BIGF;
    }
    __syncthreads();

    const int t    = blockIdx.x * blockDim.x + tid;
    const int base = t * 4;
    const bool fullv = (base + 3 < n);

    float z[4];
    int   sg[4];
    int   b0 = 0;
    bool  uni = false;

    if (fullv) {
        const float4* c4 = (const float4*)coord;
        float4 ca = c4[3 * t + 0];
        float4 cb = c4[3 * t + 1];
        float4 cc = c4[3 * t + 2];
        int4   s4 = ((const int4*)segment)[t];
        z[0]=ca.z; z[1]=cb.y; z[2]=cc.x; z[3]=cc.w;
        sg[0]=s4.x; sg[1]=s4.y; sg[2]=s4.z; sg[3]=s4.w;
        b0  = batch_of(base, s_off);
        uni = (b0 == batch_of(base + 3, s_off));   // batch ids monotonic
    }

    const int  wb   = __shfl_sync(FULLMASK, b0, 0);
    const bool wuni = __all_sync(FULLMASK, fullv && uni && (b0 == wb));

    if (wuni) {
        float lg = -BIGF, lp = BIGF, lmn = BIGF, lmx = -BIGF;
#pragma unroll
        for (int j = 0; j < 4; j++) {
            float zz = z[j];
            if (sg[j] == 0) lg = fmaxf(lg, zz); else lp = fminf(lp, zz);
            lmn = fminf(lmn, zz);
            lmx = fmaxf(lmx, zz);
        }
#pragma unroll
        for (int o = 16; o > 0; o >>= 1) {
            lg  = fmaxf(lg,  __shfl_xor_sync(FULLMASK, lg,  o));
            lp  = fminf(lp,  __shfl_xor_sync(FULLMASK, lp,  o));
            lmn = fminf(lmn, __shfl_xor_sync(FULLMASK, lmn, o));
            lmx = fmaxf(lmx, __shfl_xor_sync(FULLMASK, lmx, o));
        }
        if ((tid & 31) == 0) {
            if (lg > -BIGF) atomicMaxF(&s_gmax[wb], lg);
            if (lp <  BIGF) atomicMinF(&s_pmin[wb], lp);
            atomicMinF(&s_zmin[wb], lmn);
            atomicMaxF(&s_zmax[wb], lmx);
        }
    } else {
#pragma unroll
        for (int j = 0; j < 4; j++) {
            int i = base + j;
            if (i < n) {
                float zz = fullv ? z[j]  : coord[3 * i + 2];
                int   ss = fullv ? sg[j] : segment[i];
                int   b  = batch_of(i, s_off);
                if (ss == 0) atomicMaxF(&s_gmax[b], zz);
                else         atomicMinF(&s_pmin[b], zz);
                atomicMinF(&s_zmin[b], zz);
                atomicMaxF(&s_zmax[b], zz);
            }
        }
    }
    __syncthreads();

    if (tid < 32) {
        int b = tid >> 2, k = tid & 3;
        if      (k == 0) { float v = s_gmax[b]; if (v > -BIGF) atomicMaxF(&g_gmax[b], v); }
        else if (k == 1) { float v = s_pmin[b]; if (v <  BIGF) atomicMinF(&g_pmin[b], v); }
        else if (k == 2) { float v = s_zmin[b]; if (v <  BIGF) atomicMinF(&g_zmin[b], v); }
        else             { float v = s_zmax[b]; if (v > -BIGF) atomicMaxF(&g_zmax[b], v); }
    }
}

// ---------------------------------------------------------------------------
// Pass 2: loss sum, 4 points per thread, <=42 regs (6 blocks/SM)
// ---------------------------------------------------------------------------
__device__ __forceinline__ float point_loss(float x0, float x1, int s,
                                            float zz, float mu)
{
    // CE + focal via logit margin: dlt = x_true - x_other
    float dlt = s ? (x1 - x0) : (x0 - x1);
    dlt = fmaxf(dlt, -80.0f);              // overflow guard for exp
    float e   = __expf(-dlt);
    float r   = 1.0f + e;
    float inv = __frcp_rn(r);              // p_t
    float nlt = __logf(r);                 // -log p_t
    float om  = e * inv;                   // 1 - p_t
    float cef = nlt * om * om;             // CE * focal
    // branch-free asymmetric gaussian
    float d    = zz - mu;
    float dd   = d * d;
    float coef = (zz <= mu) ? -50.0f : -3.125f;
    float w    = __expf(coef * dd);
    w = (d > 0.8f) ? 0.1f : w;             // d>0.8 implies right side
    return cef * w;
}

__global__ void __launch_bounds__(256, 6)
k_loss(const float* __restrict__ pred, const float* __restrict__ coord,
       const int* __restrict__ segment, const int* __restrict__ offset,
       float* __restrict__ out, int n, int nb, int nblocks, float inv_n)
{
    __shared__ int   s_off[MAXB];
    __shared__ float s_mu[MAXB];
    __shared__ float s_part[8];
    const int tid = threadIdx.x;
    if (tid < MAXB) {
        s_off[tid] = (tid < nb) ? offset[tid] : 0x7FFFFFFF;
        float g = g_gmax[tid]; if (g <= -BIGF) g = g_zmin[tid];
        float p = g_pmin[tid]; if (p >=  BIGF) p = g_zmax[tid];
        s_mu[tid] = g + (p - g) * 0.5f;    // exact reference expression
    }
    __syncthreads();

    const int t    = blockIdx.x * blockDim.x + tid;
    const int base = t * 4;
    float acc = 0.0f;

    if (base + 3 < n) {
        // 6 independent LDG.128, front-batched.
        // pred with evict-first hint: one-time stream, don't evict coord/seg
        // lines that pass 1 left resident in L2.
        const float4* p4 = (const float4*)pred;
        float4 pa = __ldcs(&p4[2 * t + 0]);
        float4 pb = __ldcs(&p4[2 * t + 1]);
        const float4* c4 = (const float4*)coord;
        float4 ca = c4[3 * t + 0];
        float4 cb = c4[3 * t + 1];
        float4 cc = c4[3 * t + 2];
        int4   s4 = ((const int4*)segment)[t];

        float z[4]  = { ca.z, cb.y, cc.x, cc.w };
        float x0[4] = { pa.x, pa.z, pb.x, pb.z };
        float x1[4] = { pa.y, pa.w, pb.y, pb.w };
        int   sg[4] = { s4.x, s4.y, s4.z, s4.w };

        int b0 = batch_of(base, s_off);
        if (b0 == batch_of(base + 3, s_off)) {
            const float mu = s_mu[b0];
#pragma unroll
            for (int j = 0; j < 4; j++)
                acc += point_loss(x0[j], x1[j], sg[j], z[j], mu);
        } else {
#pragma unroll
            for (int j = 0; j < 4; j++) {
                int b = batch_of(base + j, s_off);
                acc += point_loss(x0[j], x1[j], sg[j], z[j], s_mu[b]);
            }
        }
    } else {
#pragma unroll
        for (int j = 0; j < 4; j++) {
            int i = base + j;
            if (i < n) {
                int b = batch_of(i, s_off);
                acc += point_loss(pred[2 * i], pred[2 * i + 1], segment[i],
                                  coord[3 * i + 2], s_mu[b]);
            }
        }
    }

#pragma unroll
    for (int o = 16; o > 0; o >>= 1)
        acc += __shfl_xor_sync(FULLMASK, acc, o);
    if ((tid & 31) == 0) s_part[tid >> 5] = acc;
    __syncthreads();

    if (tid == 0) {
        float s = 0.0f;
#pragma unroll
        for (int k = 0; k < 8; k++) s += s_part[k];
        atomicAdd(&g_acc[blockIdx.x & 31], s);
        __threadfence();
        int old = atomicAdd(&g_done, 1);
        if (old == nblocks - 1) {
            float tot = 0.0f;
#pragma unroll
            for (int k = 0; k < 32; k++)
                tot += *((volatile float*)&g_acc[k]);
            out[0] = tot * inv_n;
            // restore clean state for next graph replay
#pragma unroll
            for (int k = 0; k < 32; k++) g_acc[k] = 0.0f;
#pragma unroll
            for (int k = 0; k < MAXB; k++) {
                g_gmax[k] = -BIGF;  g_pmin[k] = BIGF;
                g_zmin[k] =  BIGF;  g_zmax[k] = -BIGF;
            }
            g_done = 0;
            __threadfence();
        }
    }
}

// ---------------------------------------------------------------------------
extern "C" void kernel_launch(void* const* d_in, const int* in_sizes, int n_in,
                              void* d_out, int out_size)
{
    const float* pred    = (const float*)d_in[0];
    const float* coord   = (const float*)d_in[1];
    const int*   segment = (const int*)d_in[2];
    const int*   offset  = (const int*)d_in[3];
    int n  = in_sizes[2];
    int nb = in_sizes[3]; if (nb > MAXB) nb = MAXB;

    const int threads = 256;
    const int ppb     = threads * 4;
    const int blocks  = (n + ppb - 1) / ppb;

    k_stats<<<blocks, threads>>>(coord, segment, offset, n, nb);
    k_loss<<<blocks, threads>>>(pred, coord, segment, offset,
                                (float*)d_out, n, nb, blocks, 1.0f / (float)n);
}

// round 12
// speedup vs baseline: 1.1044x; 1.1044x over previous
#include <cuda_runtime.h>
#include <math.h>

// ---------------------------------------------------------------------------
// GaussCrossEntropyLoss — two-pass, 8 pts/thread, zpack compaction.
// Pass 1 (k_stats): coord+segment (64 MB) -> per-cloud z stats,
//                   writes zpack[i] = (bits(z)&~1)|seg (16 MB).
// Pass 2 (k_loss):  pred (32 MB, streaming) + zpack (16 MB, L2-hot)
//                   -> sum CE*focal*gauss; last block writes mean + resets.
// ---------------------------------------------------------------------------

#define FULLMASK 0xFFFFFFFFu
#define MAXB 8
#define BIGF 3.402823466e+38f
#define CAP  4194304

// Static initializers == clean state; the last k_loss block restores them.
__device__ float g_gmax[MAXB] = {-BIGF,-BIGF,-BIGF,-BIGF,-BIGF,-BIGF,-BIGF,-BIGF};
__device__ float g_pmin[MAXB] = { BIGF, BIGF, BIGF, BIGF, BIGF, BIGF, BIGF, BIGF};
__device__ float g_zmin[MAXB] = { BIGF, BIGF, BIGF, BIGF, BIGF, BIGF, BIGF, BIGF};
__device__ float g_zmax[MAXB] = {-BIGF,-BIGF,-BIGF,-BIGF,-BIGF,-BIGF,-BIGF,-BIGF};
__device__ float g_acc[32];
__device__ int   g_done;
__device__ unsigned int g_zpack[CAP];

__device__ __forceinline__ void atomicMaxF(float* a, float v) {
    if (v >= 0.0f) atomicMax((int*)a, __float_as_int(v));
    else           atomicMin((unsigned int*)a, __float_as_uint(v));
}
__device__ __forceinline__ void atomicMinF(float* a, float v) {
    if (v >= 0.0f) atomicMin((int*)a, __float_as_int(v));
    else           atomicMax((unsigned int*)a, __float_as_uint(v));
}

__device__ __forceinline__ int batch_of(int i, const int* s_off) {
    int b = 0;
#pragma unroll
    for (int k = 0; k < MAXB; k++) b += (i >= s_off[k]);
    return b;
}

__device__ __forceinline__ unsigned int pack_zs(float z, int s) {
    return (__float_as_uint(z) & ~1u) | (unsigned int)(s & 1);
}

// ---------------------------------------------------------------------------
// Pass 1: per-cloud z statistics + zpack emission, 8 points per thread
// ---------------------------------------------------------------------------
__global__ void __launch_bounds__(256)
k_stats(const float* __restrict__ coord, const int* __restrict__ segment,
        const int* __restrict__ offset, int n, int nb, int usepack)
{
    __shared__ int   s_off[MAXB];
    __shared__ float s_gmax[MAXB], s_pmin[MAXB], s_zmin[MAXB], s_zmax[MAXB];
    const int tid = threadIdx.x;
    if (tid < MAXB) {
        s_off[tid]  = (tid < nb) ? offset[tid] : 0x7FFFFFFF;
        s_gmax[tid] = -BIGF;  s_pmin[tid] = BIGF;
        s_zmin[tid] =  BIGF;  s_zmax[tid] = -BIGF;
    }
    __syncthreads();

    const int t    = blockIdx.x * blockDim.x + tid;
    const int base = t * 8;
    const bool fullv = (base + 7 < n);

    float z[8];
    int   sg[8];
    int   b0 = 0;
    bool  uni = false;

    if (fullv) {
        const float4* c4 = (const float4*)coord;
        float4 c[6];
#pragma unroll
        for (int j = 0; j < 6; j++) c[j] = c4[6 * t + j];
        const int4* s4 = (const int4*)segment;
        int4 sa = s4[2 * t], sb = s4[2 * t + 1];
        z[0]=c[0].z; z[1]=c[1].y; z[2]=c[2].x; z[3]=c[2].w;
        z[4]=c[3].z; z[5]=c[4].y; z[6]=c[5].x; z[7]=c[5].w;
        sg[0]=sa.x; sg[1]=sa.y; sg[2]=sa.z; sg[3]=sa.w;
        sg[4]=sb.x; sg[5]=sb.y; sg[6]=sb.z; sg[7]=sb.w;
        b0  = batch_of(base, s_off);
        uni = (b0 == batch_of(base + 7, s_off));   // batch ids monotonic
        if (usepack) {
            uint4 ua = make_uint4(pack_zs(z[0],sg[0]), pack_zs(z[1],sg[1]),
                                  pack_zs(z[2],sg[2]), pack_zs(z[3],sg[3]));
            uint4 ub = make_uint4(pack_zs(z[4],sg[4]), pack_zs(z[5],sg[5]),
                                  pack_zs(z[6],sg[6]), pack_zs(z[7],sg[7]));
            ((uint4*)g_zpack)[2 * t + 0] = ua;
            ((uint4*)g_zpack)[2 * t + 1] = ub;
        }
    }

    const int  wb   = __shfl_sync(FULLMASK, b0, 0);
    const bool wuni = __all_sync(FULLMASK, fullv && uni && (b0 == wb));

    if (wuni) {
        float lg = -BIGF, lp = BIGF, lmn = BIGF, lmx = -BIGF;
#pragma unroll
        for (int j = 0; j < 8; j++) {
            float zz = z[j];
            if (sg[j] == 0) lg = fmaxf(lg, zz); else lp = fminf(lp, zz);
            lmn = fminf(lmn, zz);
            lmx = fmaxf(lmx, zz);
        }
#pragma unroll
        for (int o = 16; o > 0; o >>= 1) {
            lg  = fmaxf(lg,  __shfl_xor_sync(FULLMASK, lg,  o));
            lp  = fminf(lp,  __shfl_xor_sync(FULLMASK, lp,  o));
            lmn = fminf(lmn, __shfl_xor_sync(FULLMASK, lmn, o));
            lmx = fmaxf(lmx, __shfl_xor_sync(FULLMASK, lmx, o));
        }
        if ((tid & 31) == 0) {
            if (lg > -BIGF) atomicMaxF(&s_gmax[wb], lg);
            if (lp <  BIGF) atomicMinF(&s_pmin[wb], lp);
            atomicMinF(&s_zmin[wb], lmn);
            atomicMaxF(&s_zmax[wb], lmx);
        }
    } else {
#pragma unroll
        for (int j = 0; j < 8; j++) {
            int i = base + j;
            if (i < n) {
                float zz = fullv ? z[j]  : coord[3 * i + 2];
                int   ss = fullv ? sg[j] : segment[i];
                if (!fullv && usepack) g_zpack[i] = pack_zs(zz, ss);
                int b = batch_of(i, s_off);
                if (ss == 0) atomicMaxF(&s_gmax[b], zz);
                else         atomicMinF(&s_pmin[b], zz);
                atomicMinF(&s_zmin[b], zz);
                atomicMaxF(&s_zmax[b], zz);
            }
        }
    }
    __syncthreads();

    if (tid < 32) {
        int b = tid >> 2, k = tid & 3;
        if      (k == 0) { float v = s_gmax[b]; if (v > -BIGF) atomicMaxF(&g_gmax[b], v); }
        else if (k == 1) { float v = s_pmin[b]; if (v <  BIGF) atomicMinF(&g_pmin[b], v); }
        else if (k == 2) { float v = s_zmin[b]; if (v <  BIGF) atomicMinF(&g_zmin[b], v); }
        else             { float v = s_zmax[b]; if (v > -BIGF) atomicMaxF(&g_zmax[b], v); }
    }
}

// ---------------------------------------------------------------------------
// Pass 2: loss sum from pred + zpack, 8 points per thread
// ---------------------------------------------------------------------------
__device__ __forceinline__ float point_loss(float x0, float x1, int s,
                                            float zz, float mu)
{
    float dlt = s ? (x1 - x0) : (x0 - x1);
    dlt = fmaxf(dlt, -80.0f);
    float e   = __expf(-dlt);
    float r   = 1.0f + e;
    float inv = __frcp_rn(r);              // p_t
    float nlt = __logf(r);                 // -log p_t
    float om  = e * inv;                   // 1 - p_t
    float cef = nlt * om * om;             // CE * focal
    float d    = zz - mu;
    float dd   = d * d;
    float coef = (zz <= mu) ? -50.0f : -3.125f;
    float w    = __expf(coef * dd);
    w = (d > 0.8f) ? 0.1f : w;
    return cef * w;
}

__global__ void __launch_bounds__(256, 5)
k_loss(const float* __restrict__ pred, const float* __restrict__ coord,
       const int* __restrict__ segment, const int* __restrict__ offset,
       float* __restrict__ out, int n, int nb, int nblocks, float inv_n,
       int usepack)
{
    __shared__ int   s_off[MAXB];
    __shared__ float s_mu[MAXB];
    __shared__ float s_part[8];
    const int tid = threadIdx.x;
    if (tid < MAXB) {
        s_off[tid] = (tid < nb) ? offset[tid] : 0x7FFFFFFF;
        float g = g_gmax[tid]; if (g <= -BIGF) g = g_zmin[tid];
        float p = g_pmin[tid]; if (p >=  BIGF) p = g_zmax[tid];
        s_mu[tid] = g + (p - g) * 0.5f;    // exact reference expression
    }
    __syncthreads();

    const int t    = blockIdx.x * blockDim.x + tid;
    const int base = t * 8;
    float acc = 0.0f;

    if (base + 7 < n) {
        float z[8];
        int   sg[8];
        float x0[8], x1[8];
        // pred: streaming (one-time), 4 LDG.128
        const float4* p4 = (const float4*)pred;
        float4 p[4];
#pragma unroll
        for (int j = 0; j < 4; j++) p[j] = __ldcs(&p4[4 * t + j]);
#pragma unroll
        for (int j = 0; j < 4; j++) {
            x0[2*j] = p[j].x;  x1[2*j] = p[j].y;
            x0[2*j+1] = p[j].z; x1[2*j+1] = p[j].w;
        }
        if (usepack) {
            // zpack: 2 LDG.128, L2-hot (written by pass 1)
            uint4 ua = ((const uint4*)g_zpack)[2 * t + 0];
            uint4 ub = ((const uint4*)g_zpack)[2 * t + 1];
            unsigned int u[8] = { ua.x, ua.y, ua.z, ua.w,
                                  ub.x, ub.y, ub.z, ub.w };
#pragma unroll
            for (int j = 0; j < 8; j++) {
                sg[j] = (int)(u[j] & 1u);
                z[j]  = __uint_as_float(u[j] & ~1u);
            }
        } else {
            const float4* c4 = (const float4*)coord;
            float4 c[6];
#pragma unroll
            for (int j = 0; j < 6; j++) c[j] = c4[6 * t + j];
            const int4* s4 = (const int4*)segment;
            int4 sa = s4[2 * t], sb = s4[2 * t + 1];
            z[0]=c[0].z; z[1]=c[1].y; z[2]=c[2].x; z[3]=c[2].w;
            z[4]=c[3].z; z[5]=c[4].y; z[6]=c[5].x; z[7]=c[5].w;
            sg[0]=sa.x; sg[1]=sa.y; sg[2]=sa.z; sg[3]=sa.w;
            sg[4]=sb.x; sg[5]=sb.y; sg[6]=sb.z; sg[7]=sb.w;
        }

        int b0 = batch_of(base, s_off);
        if (b0 == batch_of(base + 7, s_off)) {
            const float mu = s_mu[b0];
#pragma unroll
            for (int j = 0; j < 8; j++)
                acc += point_loss(x0[j], x1[j], sg[j], z[j], mu);
        } else {
#pragma unroll
            for (int j = 0; j < 8; j++) {
                int b = batch_of(base + j, s_off);
                acc += point_loss(x0[j], x1[j], sg[j], z[j], s_mu[b]);
            }
        }
    } else {
#pragma unroll
        for (int j = 0; j < 8; j++) {
            int i = base + j;
            if (i < n) {
                float zz; int ss;
                if (usepack) {
                    unsigned int u = g_zpack[i];
                    ss = (int)(u & 1u);
                    zz = __uint_as_float(u & ~1u);
                } else {
                    zz = coord[3 * i + 2];
                    ss = segment[i];
                }
                int b = batch_of(i, s_off);
                acc += point_loss(pred[2 * i], pred[2 * i + 1], ss, zz, s_mu[b]);
            }
        }
    }

#pragma unroll
    for (int o = 16; o > 0; o >>= 1)
        acc += __shfl_xor_sync(FULLMASK, acc, o);
    if ((tid & 31) == 0) s_part[tid >> 5] = acc;
    __syncthreads();

    if (tid == 0) {
        float s = 0.0f;
#pragma unroll
        for (int k = 0; k < 8; k++) s += s_part[k];
        atomicAdd(&g_acc[blockIdx.x & 31], s);
        __threadfence();
        int old = atomicAdd(&g_done, 1);
        if (old == nblocks - 1) {
            float tot = 0.0f;
#pragma unroll
            for (int k = 0; k < 32; k++)
                tot += *((volatile float*)&g_acc[k]);
            out[0] = tot * inv_n;
            // restore clean state for next graph replay
#pragma unroll
            for (int k = 0; k < 32; k++) g_acc[k] = 0.0f;
#pragma unroll
            for (int k = 0; k < MAXB; k++) {
                g_gmax[k] = -BIGF;  g_pmin[k] = BIGF;
                g_zmin[k] =  BIGF;  g_zmax[k] = -BIGF;
            }
            g_done = 0;
            __threadfence();
        }
    }
}

// ---------------------------------------------------------------------------
extern "C" void kernel_launch(void* const* d_in, const int* in_sizes, int n_in,
                              void* d_out, int out_size)
{
    const float* pred    = (const float*)d_in[0];
    const float* coord   = (const float*)d_in[1];
    const int*   segment = (const int*)d_in[2];
    const int*   offset  = (const int*)d_in[3];
    int n  = in_sizes[2];
    int nb = in_sizes[3]; if (nb > MAXB) nb = MAXB;
    int usepack = (n <= CAP) ? 1 : 0;

    const int threads = 256;
    const int ppb     = threads * 8;
    const int blocks  = (n + ppb - 1) / ppb;

    k_stats<<<blocks, threads>>>(coord, segment, offset, n, nb, usepack);
    k_loss<<<blocks, threads>>>(pred, coord, segment, offset,
                                (float*)d_out, n, nb, blocks,
                                1.0f / (float)n, usepack);
}